// round 7
// baseline (speedup 1.0000x reference)
#include <cuda_runtime.h>
#include <cstdint>

// ---------------------------------------------------------------------------
// SageLayer: out = relu(concat(features, segsum(features[col], row)/(deg+1)) @ W)
// features: f32 [N,64], row/col: int32 [E] (JAX silently downcasts int64->int32),
// W: f32 [128,128], out: f32 [N,128]
// ---------------------------------------------------------------------------

#define N_NODES_MAX 50000

// Scratch (allocation-free rule: __device__ globals)
__device__ __align__(16) float g_acc[N_NODES_MAX * 64];  // neighbor feature sums
__device__ float g_deg[N_NODES_MAX];                     // degree + 1

// ---------------------------------------------------------------------------
// Kernel 1: init accumulator to 0, degree to 1.0 (the "+1")
// ---------------------------------------------------------------------------
__global__ void sage_init_kernel(int n) {
    int tid = blockIdx.x * blockDim.x + threadIdx.x;
    int stride = gridDim.x * blockDim.x;
    float4* acc4 = reinterpret_cast<float4*>(g_acc);
    int n4 = n * 16;  // 64 floats = 16 float4 per node
    for (int i = tid; i < n4; i += stride)
        acc4[i] = make_float4(0.f, 0.f, 0.f, 0.f);
    for (int i = tid; i < n; i += stride)
        g_deg[i] = 1.0f;
}

// ---------------------------------------------------------------------------
// Kernel 2: edge scatter. 16 threads per edge, each moves one float4 via
// vectorized global reduction (red.global.add.v4.f32, sm_90+).
// ---------------------------------------------------------------------------
__global__ void sage_scatter_kernel(const float4* __restrict__ feat4,
                                    const int* __restrict__ row,
                                    const int* __restrict__ col,
                                    int nedges) {
    int tid = blockIdx.x * blockDim.x + threadIdx.x;
    int e = tid >> 4;
    int lane = tid & 15;
    if (e >= nedges) return;

    int r = __ldg(&row[e]);
    int c = __ldg(&col[e]);

    float4 v = __ldg(&feat4[(size_t)c * 16 + lane]);
    float4* dst = reinterpret_cast<float4*>(g_acc) + (size_t)r * 16 + lane;
    asm volatile("red.global.add.v4.f32 [%0], {%1, %2, %3, %4};"
                 :: "l"(dst), "f"(v.x), "f"(v.y), "f"(v.z), "f"(v.w)
                 : "memory");
    if (lane == 0) {
        asm volatile("red.global.add.f32 [%0], %1;"
                     :: "l"(&g_deg[r]), "f"(1.0f) : "memory");
    }
}

// ---------------------------------------------------------------------------
// Kernel 3: fused normalize + concat + GEMM(128x128) + ReLU.
// One block = 32 rows. W (64KB) + combined tile (16KB) in dynamic smem.
// 256 threads, each computes a 4x4 (row x col) microtile.
// ---------------------------------------------------------------------------
__global__ __launch_bounds__(256, 2)
void sage_gemm_kernel(const float* __restrict__ feat,
                      const float* __restrict__ W,
                      float* __restrict__ out,
                      int n) {
    extern __shared__ float sh[];
    float* sW = sh;            // 128*128 = 16384 floats
    float* sC = sh + 16384;    // 32*128  =  4096 floats

    int t = threadIdx.x;
    int row0 = blockIdx.x * 32;

    // Stage W (row-major [128,128]) into smem via float4
    {
        float4* sW4 = reinterpret_cast<float4*>(sW);
        const float4* W4 = reinterpret_cast<const float4*>(W);
        #pragma unroll
        for (int i = t; i < 4096; i += 256)
            sW4[i] = __ldg(&W4[i]);
    }

    // Stage combined tile: cols [0,64) = features, [64,128) = acc/deg
    {
        float4* sC4 = reinterpret_cast<float4*>(sC);
        const float4* feat4 = reinterpret_cast<const float4*>(feat);
        const float4* acc4 = reinterpret_cast<const float4*>(g_acc);
        for (int i = t; i < 1024; i += 256) {   // 32 rows x 32 float4
            int r = i >> 5;
            int q = i & 31;
            int gr = row0 + r;
            float4 v = make_float4(0.f, 0.f, 0.f, 0.f);
            if (gr < n) {
                if (q < 16) {
                    v = __ldg(&feat4[(size_t)gr * 16 + q]);
                } else {
                    float inv = 1.0f / g_deg[gr];
                    float4 a = acc4[(size_t)gr * 16 + (q - 16)];
                    v = make_float4(a.x * inv, a.y * inv, a.z * inv, a.w * inv);
                }
            }
            sC4[i] = v;
        }
    }
    __syncthreads();

    // 4x4 microtile: thread group tr handles rows [tr*4, tr*4+4),
    // lane group tc handles cols [tc*4, tc*4+4)
    int tr = t >> 5;   // 0..7  -> row group (4 rows)
    int tc = t & 31;   // 0..31 -> col group (4 cols)

    float acc[4][4];
    #pragma unroll
    for (int i = 0; i < 4; i++)
        #pragma unroll
        for (int j = 0; j < 4; j++)
            acc[i][j] = 0.f;

    const float* cr0 = sC + (tr * 4 + 0) * 128;
    const float* cr1 = sC + (tr * 4 + 1) * 128;
    const float* cr2 = sC + (tr * 4 + 2) * 128;
    const float* cr3 = sC + (tr * 4 + 3) * 128;

    #pragma unroll 4
    for (int k = 0; k < 128; k++) {
        float4 b = reinterpret_cast<float4*>(sW + k * 128)[tc];
        float a0 = cr0[k];
        float a1 = cr1[k];
        float a2 = cr2[k];
        float a3 = cr3[k];
        acc[0][0] += a0 * b.x; acc[0][1] += a0 * b.y; acc[0][2] += a0 * b.z; acc[0][3] += a0 * b.w;
        acc[1][0] += a1 * b.x; acc[1][1] += a1 * b.y; acc[1][2] += a1 * b.z; acc[1][3] += a1 * b.w;
        acc[2][0] += a2 * b.x; acc[2][1] += a2 * b.y; acc[2][2] += a2 * b.z; acc[2][3] += a2 * b.w;
        acc[3][0] += a3 * b.x; acc[3][1] += a3 * b.y; acc[3][2] += a3 * b.z; acc[3][3] += a3 * b.w;
    }

    // ReLU + store (float4 per row)
    #pragma unroll
    for (int i = 0; i < 4; i++) {
        int gr = row0 + tr * 4 + i;
        if (gr < n) {
            float4 o;
            o.x = fmaxf(acc[i][0], 0.f);
            o.y = fmaxf(acc[i][1], 0.f);
            o.z = fmaxf(acc[i][2], 0.f);
            o.w = fmaxf(acc[i][3], 0.f);
            reinterpret_cast<float4*>(out)[(size_t)gr * 32 + tc] = o;
        }
    }
}

// ---------------------------------------------------------------------------
// Launch
// ---------------------------------------------------------------------------
extern "C" void kernel_launch(void* const* d_in, const int* in_sizes, int n_in,
                              void* d_out, int out_size) {
    const float* feat = (const float*)d_in[0];   // [N,64]
    const int* row = (const int*)d_in[1];        // [E] int32 (JAX x64 disabled)
    const int* col = (const int*)d_in[2];        // [E] int32
    const float* W = (const float*)d_in[3];      // [128,128]
    float* out = (float*)d_out;                  // [N,128]

    int n = in_sizes[0] / 64;
    int nedges = in_sizes[1];

    // 1) init scratch
    sage_init_kernel<<<1024, 256>>>(n);

    // 2) edge scatter: 16 threads/edge
    {
        long long total = (long long)nedges * 16;
        int blocks = (int)((total + 255) / 256);
        sage_scatter_kernel<<<blocks, 256>>>(
            reinterpret_cast<const float4*>(feat), row, col, nedges);
    }

    // 3) fused normalize + GEMM + ReLU
    {
        int smem = (16384 + 4096) * sizeof(float);  // 80 KB
        cudaFuncSetAttribute(sage_gemm_kernel,
                             cudaFuncAttributeMaxDynamicSharedMemorySize, smem);
        int blocks = (n + 31) / 32;
        sage_gemm_kernel<<<blocks, 256, smem>>>(feat, W, out, n);
    }
}